// round 2
// baseline (speedup 1.0000x reference)
#include <cuda_runtime.h>
#include <cuda_bf16.h>
#include <cstdint>

#define NN 100000
#define EE 1600000
#define DD 128
#define LL 4
#define LN_EPS 1e-5f
#define NTILES 782            // ceil(NN/128)
#define GRID_PERSIST 148

// ---------------- device scratch (static, allocation-free) ----------------
__device__ int   g_deg[NN];
__device__ int   g_cnt[NN];
__device__ int   g_row_ptr[NN + 1];
__device__ int   g_csr_src[EE];
__device__ float g_bufA[NN * DD];
__device__ float g_bufB[NN * DD];
__device__ float g_wperm[LL * 32 * 32 * 32];   // fragment-ordered tf32 weights, all layers
__device__ int   g_tile_ctr[LL];

// ---------------- helpers ----------------
__device__ __forceinline__ uint32_t f2tf32(float f) {
    uint32_t r;
    asm("cvt.rna.tf32.f32 %0, %1;" : "=r"(r) : "f"(f));
    return r;
}

__device__ __forceinline__ void mma_tf32(float c[4],
                                         uint32_t a0, uint32_t a1, uint32_t a2, uint32_t a3,
                                         uint32_t b0, uint32_t b1) {
    asm volatile(
        "mma.sync.aligned.m16n8k8.row.col.f32.tf32.tf32.f32 "
        "{%0,%1,%2,%3},{%4,%5,%6,%7},{%8,%9},{%0,%1,%2,%3};\n"
        : "+f"(c[0]), "+f"(c[1]), "+f"(c[2]), "+f"(c[3])
        : "r"(a0), "r"(a1), "r"(a2), "r"(a3), "r"(b0), "r"(b1));
}

__device__ __forceinline__ void add4(float4& a, const float4 b) {
    a.x += b.x; a.y += b.y; a.z += b.z; a.w += b.w;
}

// ---------------- preprocessing kernels ----------------
__global__ void zero_kernel() {
    int i = blockIdx.x * blockDim.x + threadIdx.x;
    if (i < NN) { g_deg[i] = 0; g_cnt[i] = 0; }
    if (i < LL) g_tile_ctr[i] = 0;
}

__global__ void hist_kernel(const int* __restrict__ dst) {
    int e = blockIdx.x * blockDim.x + threadIdx.x;
    if (e < EE) atomicAdd(&g_deg[dst[e]], 1);
}

// exclusive scan of g_deg -> g_row_ptr, single block of 1024 threads
__global__ void scan_kernel() {
    __shared__ int wsum[32];
    __shared__ int sh_carry;
    int tid = threadIdx.x, lane = tid & 31, warp = tid >> 5;
    if (tid == 0) sh_carry = 0;
    __syncthreads();
    for (int base = 0; base < NN; base += 1024) {
        int i = base + tid;
        int v = (i < NN) ? g_deg[i] : 0;
        int x = v;
        #pragma unroll
        for (int m = 1; m < 32; m <<= 1) {
            int y = __shfl_up_sync(0xffffffffu, x, m);
            if (lane >= m) x += y;
        }
        if (lane == 31) wsum[warp] = x;
        __syncthreads();
        if (warp == 0) {
            int s = wsum[lane];
            #pragma unroll
            for (int m = 1; m < 32; m <<= 1) {
                int y = __shfl_up_sync(0xffffffffu, s, m);
                if (lane >= m) s += y;
            }
            wsum[lane] = s;
        }
        __syncthreads();
        int off = (warp > 0 ? wsum[warp - 1] : 0) + sh_carry;
        if (i < NN) g_row_ptr[i] = off + x - v;
        int total = wsum[31];
        __syncthreads();
        if (tid == 0) sh_carry += total;
        __syncthreads();
    }
    if (threadIdx.x == 0) g_row_ptr[NN] = sh_carry;
}

__global__ void scatter_kernel(const int* __restrict__ src, const int* __restrict__ dst) {
    int e = blockIdx.x * blockDim.x + threadIdx.x;
    if (e < EE) {
        int d = dst[e];
        int pos = g_row_ptr[d] + atomicAdd(&g_cnt[d], 1);
        g_csr_src[pos] = src[e];
    }
}

// ---------------- weight permutation, all layers at once ----------------
// g_wperm[l][(kk*32+lane)*32 + j] = Wcomb[kk*8 + tig + (j&1)*4][(j>>1)*8 + g]
// Wcomb rows 0..127 = W_rel[l], 128..255 = W_root[l]; lane = g*4+tig
__global__ void wprep_kernel(const float* __restrict__ W_rel, const float* __restrict__ W_root) {
    int gi = blockIdx.x * blockDim.x + threadIdx.x;   // 0..4*32768-1
    int l = gi >> 15;
    int idx = gi & 32767;
    int kk = idx >> 10;
    int lane = (idx >> 5) & 31;
    int j = idx & 31;
    int g = lane >> 2, tig = lane & 3;
    int krow = kk * 8 + tig + (j & 1) * 4;
    int col = (j >> 1) * 8 + g;
    float v = (krow < 128) ? W_rel[l * DD * DD + krow * 128 + col]
                           : W_root[l * DD * DD + (krow - 128) * 128 + col];
    g_wperm[gi] = __uint_as_float(f2tf32(v));
}

// ---------------- fused agg + GEMM + bias + residual + ReLU + LayerNorm ----------------
// out[tile rows] = (sum_{j->i} Hin[j]) @ W_rel + bias + Hin @ W_root  (tf32 mma, K=256 stacked)
struct GSmem {
    float w[32][32][36];   // [kk][lane][j] padded 32->36 for conflict-free LDS.128
    float a[128][132];     // A tile, padded stride
    float bias[128];
    float gamma[128];
    float beta[128];
};

__global__ void __launch_bounds__(256, 1)
fused_layer_kernel(const float* __restrict__ Hin,
                   const float* __restrict__ bias,
                   const float* __restrict__ gamma,
                   const float* __restrict__ beta,
                   float* __restrict__ out,
                   int layer, int do_ln, int do_resid) {
    extern __shared__ char smem_raw[];
    GSmem& s = *(GSmem*)smem_raw;
    __shared__ int sh_tile;
    int tid = threadIdx.x, warp = tid >> 5, lane = tid & 31;
    int g = lane >> 2, tig = lane & 3;

    // load fragment-ordered weights for this layer (once per CTA)
    const float* wsrc = g_wperm + layer * 32768;
    for (int i = tid; i < 32768; i += 256) {
        int kk = i >> 10, ln = (i >> 5) & 31, j = i & 31;
        s.w[kk][ln][j] = wsrc[i];
    }
    if (tid < 128) {
        s.bias[tid]  = bias[tid];
        s.gamma[tid] = gamma[tid];
        s.beta[tid]  = beta[tid];
    }
    const float4* __restrict__ H4 = (const float4*)Hin;

    while (true) {
        __syncthreads();                       // s.a free, sh_tile consumed
        if (tid == 0) sh_tile = atomicAdd(&g_tile_ctr[layer], 1);
        __syncthreads();
        int tile = sh_tile;
        if (tile >= NTILES) break;
        int rowBase = tile * 128;

        // ---- gather-aggregate neighbors into s.a (phase-0 A tile) ----
        #pragma unroll 1
        for (int rr = 0; rr < 16; ++rr) {
            int row = warp * 16 + rr;
            int grow = rowBase + row;
            float4 a0 = make_float4(0.f, 0.f, 0.f, 0.f);
            if (grow < NN) {
                float4 a1 = a0, a2 = a0, a3 = a0, a4 = a0, a5 = a0, a6 = a0, a7 = a0;
                int e = g_row_ptr[grow], end = g_row_ptr[grow + 1];
                for (; e + 8 <= end; e += 8) {
                    int s0 = __ldg(&g_csr_src[e + 0]);
                    int s1 = __ldg(&g_csr_src[e + 1]);
                    int s2 = __ldg(&g_csr_src[e + 2]);
                    int s3 = __ldg(&g_csr_src[e + 3]);
                    int s4 = __ldg(&g_csr_src[e + 4]);
                    int s5 = __ldg(&g_csr_src[e + 5]);
                    int s6 = __ldg(&g_csr_src[e + 6]);
                    int s7 = __ldg(&g_csr_src[e + 7]);
                    add4(a0, __ldg(&H4[s0 * 32 + lane]));
                    add4(a1, __ldg(&H4[s1 * 32 + lane]));
                    add4(a2, __ldg(&H4[s2 * 32 + lane]));
                    add4(a3, __ldg(&H4[s3 * 32 + lane]));
                    add4(a4, __ldg(&H4[s4 * 32 + lane]));
                    add4(a5, __ldg(&H4[s5 * 32 + lane]));
                    add4(a6, __ldg(&H4[s6 * 32 + lane]));
                    add4(a7, __ldg(&H4[s7 * 32 + lane]));
                }
                for (; e + 2 <= end; e += 2) {
                    int s0 = __ldg(&g_csr_src[e + 0]);
                    int s1 = __ldg(&g_csr_src[e + 1]);
                    add4(a0, __ldg(&H4[s0 * 32 + lane]));
                    add4(a1, __ldg(&H4[s1 * 32 + lane]));
                }
                if (e < end) {
                    int s0 = __ldg(&g_csr_src[e]);
                    add4(a2, __ldg(&H4[s0 * 32 + lane]));
                }
                add4(a0, a1); add4(a2, a3); add4(a4, a5); add4(a6, a7);
                add4(a0, a2); add4(a4, a6); add4(a0, a4);
            }
            *(float4*)&s.a[row][lane * 4] = a0;
        }
        __syncthreads();

        float c[16][4];
        #pragma unroll
        for (int nt = 0; nt < 16; nt++)
            #pragma unroll
            for (int j = 0; j < 4; j++) c[nt][j] = 0.f;

        int r0 = warp * 16 + g;

        // ---- phase 0: agg @ W_rel (kk 0..15) ----
        #pragma unroll 4
        for (int kks = 0; kks < 16; kks++) {
            uint32_t A0 = f2tf32(s.a[r0][kks * 8 + tig]);
            uint32_t A1 = f2tf32(s.a[r0 + 8][kks * 8 + tig]);
            uint32_t A2 = f2tf32(s.a[r0][kks * 8 + tig + 4]);
            uint32_t A3 = f2tf32(s.a[r0 + 8][kks * 8 + tig + 4]);
            const float4* wp = (const float4*)&s.w[kks][lane][0];
            #pragma unroll
            for (int q = 0; q < 8; q++) {
                float4 b = wp[q];
                mma_tf32(c[2 * q],     A0, A1, A2, A3, __float_as_uint(b.x), __float_as_uint(b.y));
                mma_tf32(c[2 * q + 1], A0, A1, A2, A3, __float_as_uint(b.z), __float_as_uint(b.w));
            }
        }
        __syncthreads();

        // ---- load Hin tile into s.a ----
        #pragma unroll
        for (int i = 0; i < 16; i++) {
            int f = tid + i * 256;
            int row = f >> 5, c4 = f & 31;
            int grow = rowBase + row;
            float4 v = (grow < NN) ? __ldg(&H4[grow * 32 + c4]) : make_float4(0.f, 0.f, 0.f, 0.f);
            *(float4*)&s.a[row][c4 * 4] = v;
        }
        __syncthreads();

        // ---- phase 1: Hin @ W_root (kk 16..31) ----
        #pragma unroll 4
        for (int kks = 0; kks < 16; kks++) {
            uint32_t A0 = f2tf32(s.a[r0][kks * 8 + tig]);
            uint32_t A1 = f2tf32(s.a[r0 + 8][kks * 8 + tig]);
            uint32_t A2 = f2tf32(s.a[r0][kks * 8 + tig + 4]);
            uint32_t A3 = f2tf32(s.a[r0 + 8][kks * 8 + tig + 4]);
            const float4* wp = (const float4*)&s.w[16 + kks][lane][0];
            #pragma unroll
            for (int q = 0; q < 8; q++) {
                float4 b = wp[q];
                mma_tf32(c[2 * q],     A0, A1, A2, A3, __float_as_uint(b.x), __float_as_uint(b.y));
                mma_tf32(c[2 * q + 1], A0, A1, A2, A3, __float_as_uint(b.z), __float_as_uint(b.w));
            }
        }

        // ------------- epilogue -------------
        int rA = rowBase + warp * 16 + g;
        int rB = rA + 8;
        int lrA = warp * 16 + g;
        int lrB = lrA + 8;

        #pragma unroll
        for (int nt = 0; nt < 16; nt++) {
            int col = nt * 8 + 2 * tig;
            float b0 = s.bias[col], b1 = s.bias[col + 1];
            c[nt][0] += b0; c[nt][1] += b1;
            c[nt][2] += b0; c[nt][3] += b1;
        }
        if (do_resid) {
            // residual from SMEM copy of Hin tile (still resident in s.a)
            #pragma unroll
            for (int nt = 0; nt < 16; nt++) {
                int col = nt * 8 + 2 * tig;
                c[nt][0] += s.a[lrA][col];
                c[nt][1] += s.a[lrA][col + 1];
                c[nt][2] += s.a[lrB][col];
                c[nt][3] += s.a[lrB][col + 1];
            }
        }
        if (do_ln) {
            float sA = 0.f, qA = 0.f, sB = 0.f, qB = 0.f;
            #pragma unroll
            for (int nt = 0; nt < 16; nt++) {
                #pragma unroll
                for (int j = 0; j < 4; j++) c[nt][j] = fmaxf(c[nt][j], 0.f);
                sA += c[nt][0] + c[nt][1];
                qA += c[nt][0] * c[nt][0] + c[nt][1] * c[nt][1];
                sB += c[nt][2] + c[nt][3];
                qB += c[nt][2] * c[nt][2] + c[nt][3] * c[nt][3];
            }
            #pragma unroll
            for (int m = 1; m < 4; m <<= 1) {
                sA += __shfl_xor_sync(0xffffffffu, sA, m);
                qA += __shfl_xor_sync(0xffffffffu, qA, m);
                sB += __shfl_xor_sync(0xffffffffu, sB, m);
                qB += __shfl_xor_sync(0xffffffffu, qB, m);
            }
            float muA = sA * (1.f / 128.f);
            float vA = qA * (1.f / 128.f) - muA * muA;
            float rsA = rsqrtf(vA + LN_EPS);
            float muB = sB * (1.f / 128.f);
            float vB = qB * (1.f / 128.f) - muB * muB;
            float rsB = rsqrtf(vB + LN_EPS);
            #pragma unroll
            for (int nt = 0; nt < 16; nt++) {
                int col = nt * 8 + 2 * tig;
                float g0 = s.gamma[col], g1 = s.gamma[col + 1];
                float e0 = s.beta[col],  e1 = s.beta[col + 1];
                c[nt][0] = (c[nt][0] - muA) * rsA * g0 + e0;
                c[nt][1] = (c[nt][1] - muA) * rsA * g1 + e1;
                c[nt][2] = (c[nt][2] - muB) * rsB * g0 + e0;
                c[nt][3] = (c[nt][3] - muB) * rsB * g1 + e1;
            }
        }
        if (rA < NN) {
            #pragma unroll
            for (int nt = 0; nt < 16; nt++) {
                int col = nt * 8 + 2 * tig;
                *(float2*)(out + rA * 128 + col) = make_float2(c[nt][0], c[nt][1]);
            }
        }
        if (rB < NN) {
            #pragma unroll
            for (int nt = 0; nt < 16; nt++) {
                int col = nt * 8 + 2 * tig;
                *(float2*)(out + rB * 128 + col) = make_float2(c[nt][2], c[nt][3]);
            }
        }
    }
}

// ---------------- host driver ----------------
extern "C" void kernel_launch(void* const* d_in, const int* in_sizes, int n_in,
                              void* d_out, int out_size) {
    const float* in_feat = (const float*)d_in[0];
    const int*   ei      = (const int*)d_in[1];
    const float* W_rel   = (const float*)d_in[2];
    const float* b_rel   = (const float*)d_in[3];
    const float* W_root  = (const float*)d_in[4];
    const float* gamma   = (const float*)d_in[5];
    const float* beta    = (const float*)d_in[6];
    float* out = (float*)d_out;

    const int* src = ei;
    const int* dst = ei + EE;

    cudaFuncSetAttribute(fused_layer_kernel, cudaFuncAttributeMaxDynamicSharedMemorySize,
                         (int)sizeof(GSmem));

    float* bufA = nullptr;
    float* bufB = nullptr;
    cudaGetSymbolAddress((void**)&bufA, g_bufA);
    cudaGetSymbolAddress((void**)&bufB, g_bufB);

    // CSR build + weight prep (once per launch; reused by all 4 layers)
    zero_kernel<<<(NN + 255) / 256, 256>>>();
    hist_kernel<<<(EE + 255) / 256, 256>>>(dst);
    scan_kernel<<<1, 1024>>>();
    scatter_kernel<<<(EE + 255) / 256, 256>>>(src, dst);
    wprep_kernel<<<(LL * 32768) / 256, 256>>>(W_rel, W_root);

    const float* hin = in_feat;
    for (int l = 0; l < LL; l++) {
        float* hout = (l == LL - 1) ? out : ((l & 1) ? bufB : bufA);
        int do_ln = (l < LL - 1) ? 1 : 0;
        int do_resid = (l >= 1 && l <= LL - 2) ? 1 : 0;
        fused_layer_kernel<<<GRID_PERSIST, 256, sizeof(GSmem)>>>(
            hin, b_rel + l * DD, gamma, beta, hout, l, do_ln, do_resid);
        hin = hout;
    }
}

// round 3
// speedup vs baseline: 1.5382x; 1.5382x over previous
#include <cuda_runtime.h>
#include <cuda_bf16.h>
#include <cstdint>

#define NN 100000
#define EE 1600000
#define DD 128
#define LL 4
#define LN_EPS 1e-5f
#define NTILES 782            // ceil(NN/128)
#define GRID_PERSIST 148

// ---------------- device scratch (static, allocation-free) ----------------
__device__ int   g_deg[NN];
__device__ int   g_cnt[NN];
__device__ int   g_row_ptr[NN + 1];
__device__ int   g_csr_src[EE];
__device__ float g_bufA[NN * DD];
__device__ float g_bufB[NN * DD];
__device__ float g_agg[NN * DD];
__device__ float g_wperm[LL * 32 * 32 * 32];   // fragment-ordered tf32 weights, all layers
__device__ int   g_tile_ctr[LL];

// ---------------- helpers ----------------
__device__ __forceinline__ uint32_t f2tf32(float f) {
    uint32_t r;
    asm("cvt.rna.tf32.f32 %0, %1;" : "=r"(r) : "f"(f));
    return r;
}

__device__ __forceinline__ void mma_tf32(float c[4],
                                         uint32_t a0, uint32_t a1, uint32_t a2, uint32_t a3,
                                         uint32_t b0, uint32_t b1) {
    asm volatile(
        "mma.sync.aligned.m16n8k8.row.col.f32.tf32.tf32.f32 "
        "{%0,%1,%2,%3},{%4,%5,%6,%7},{%8,%9},{%0,%1,%2,%3};\n"
        : "+f"(c[0]), "+f"(c[1]), "+f"(c[2]), "+f"(c[3])
        : "r"(a0), "r"(a1), "r"(a2), "r"(a3), "r"(b0), "r"(b1));
}

__device__ __forceinline__ void add4(float4& a, const float4 b) {
    a.x += b.x; a.y += b.y; a.z += b.z; a.w += b.w;
}

__device__ __forceinline__ void cp_async16(uint32_t smem_addr, const void* gptr, int src_bytes) {
    asm volatile("cp.async.cg.shared.global [%0], [%1], 16, %2;\n"
                 :: "r"(smem_addr), "l"(gptr), "r"(src_bytes));
}
__device__ __forceinline__ void cp_async_commit_wait0() {
    asm volatile("cp.async.commit_group;\n cp.async.wait_group 0;\n" ::: "memory");
}

// ---------------- preprocessing kernels ----------------
__global__ void zero_kernel() {
    int i = blockIdx.x * blockDim.x + threadIdx.x;
    if (i < NN) { g_deg[i] = 0; g_cnt[i] = 0; }
    if (i < LL) g_tile_ctr[i] = 0;
}

__global__ void hist_kernel(const int* __restrict__ dst) {
    int e = blockIdx.x * blockDim.x + threadIdx.x;
    if (e < EE) atomicAdd(&g_deg[dst[e]], 1);
}

// exclusive scan of g_deg -> g_row_ptr, single block of 1024 threads, int4 per thread
__global__ void scan_kernel() {
    __shared__ int wsum[32];
    __shared__ int sh_carry;
    int tid = threadIdx.x, lane = tid & 31, warp = tid >> 5;
    if (tid == 0) sh_carry = 0;
    __syncthreads();
    for (int base = 0; base < NN; base += 4096) {
        int i0 = base + tid * 4;
        int v0 = 0, v1 = 0, v2 = 0, v3 = 0;
        if (i0 + 3 < NN) {
            int4 v = *(const int4*)&g_deg[i0];
            v0 = v.x; v1 = v.y; v2 = v.z; v3 = v.w;
        } else {
            if (i0 + 0 < NN) v0 = g_deg[i0 + 0];
            if (i0 + 1 < NN) v1 = g_deg[i0 + 1];
            if (i0 + 2 < NN) v2 = g_deg[i0 + 2];
            if (i0 + 3 < NN) v3 = g_deg[i0 + 3];
        }
        int p0 = 0, p1 = v0, p2 = v0 + v1, p3 = v0 + v1 + v2;
        int tsum = p3 + v3;
        int x = tsum;
        #pragma unroll
        for (int m = 1; m < 32; m <<= 1) {
            int y = __shfl_up_sync(0xffffffffu, x, m);
            if (lane >= m) x += y;
        }
        if (lane == 31) wsum[warp] = x;
        __syncthreads();
        if (warp == 0) {
            int s = wsum[lane];
            #pragma unroll
            for (int m = 1; m < 32; m <<= 1) {
                int y = __shfl_up_sync(0xffffffffu, s, m);
                if (lane >= m) s += y;
            }
            wsum[lane] = s;
        }
        __syncthreads();
        int off = (warp > 0 ? wsum[warp - 1] : 0) + sh_carry + (x - tsum);
        if (i0 + 3 < NN) {
            *(int4*)&g_row_ptr[i0] = make_int4(off + p0, off + p1, off + p2, off + p3);
        } else {
            if (i0 + 0 < NN) g_row_ptr[i0 + 0] = off + p0;
            if (i0 + 1 < NN) g_row_ptr[i0 + 1] = off + p1;
            if (i0 + 2 < NN) g_row_ptr[i0 + 2] = off + p2;
            if (i0 + 3 < NN) g_row_ptr[i0 + 3] = off + p3;
        }
        int total = wsum[31];
        __syncthreads();
        if (tid == 0) sh_carry += total;
        __syncthreads();
    }
    if (threadIdx.x == 0) g_row_ptr[NN] = sh_carry;
}

__global__ void scatter_kernel(const int* __restrict__ src, const int* __restrict__ dst) {
    int e = blockIdx.x * blockDim.x + threadIdx.x;
    if (e < EE) {
        int d = dst[e];
        int pos = g_row_ptr[d] + atomicAdd(&g_cnt[d], 1);
        g_csr_src[pos] = src[e];
    }
}

// ---------------- weight permutation, all layers at once ----------------
__global__ void wprep_kernel(const float* __restrict__ W_rel, const float* __restrict__ W_root) {
    int gi = blockIdx.x * blockDim.x + threadIdx.x;   // 0..4*32768-1
    int l = gi >> 15;
    int idx = gi & 32767;
    int kk = idx >> 10;
    int lane = (idx >> 5) & 31;
    int j = idx & 31;
    int g = lane >> 2, tig = lane & 3;
    int krow = kk * 8 + tig + (j & 1) * 4;
    int col = (j >> 1) * 8 + g;
    float v = (krow < 128) ? W_rel[l * DD * DD + krow * 128 + col]
                           : W_root[l * DD * DD + (krow - 128) * 128 + col];
    g_wperm[gi] = __uint_as_float(f2tf32(v));
}

// ---------------- aggregation: agg[i] = sum_{e: dst=i} h[src_e] ----------------
__global__ void __launch_bounds__(256)
agg_kernel(const float* __restrict__ h) {
    int gw = (blockIdx.x * blockDim.x + threadIdx.x) >> 5;
    int lane = threadIdx.x & 31;
    if (gw >= NN) return;
    int beg = g_row_ptr[gw], end = g_row_ptr[gw + 1];
    const float4* __restrict__ h4 = (const float4*)h;
    float4 a0 = make_float4(0.f, 0.f, 0.f, 0.f);
    float4 a1 = a0, a2 = a0, a3 = a0, a4 = a0, a5 = a0, a6 = a0, a7 = a0;
    int e = beg;
    for (; e + 8 <= end; e += 8) {
        int s0 = __ldg(&g_csr_src[e + 0]);
        int s1 = __ldg(&g_csr_src[e + 1]);
        int s2 = __ldg(&g_csr_src[e + 2]);
        int s3 = __ldg(&g_csr_src[e + 3]);
        int s4 = __ldg(&g_csr_src[e + 4]);
        int s5 = __ldg(&g_csr_src[e + 5]);
        int s6 = __ldg(&g_csr_src[e + 6]);
        int s7 = __ldg(&g_csr_src[e + 7]);
        add4(a0, __ldg(&h4[s0 * 32 + lane]));
        add4(a1, __ldg(&h4[s1 * 32 + lane]));
        add4(a2, __ldg(&h4[s2 * 32 + lane]));
        add4(a3, __ldg(&h4[s3 * 32 + lane]));
        add4(a4, __ldg(&h4[s4 * 32 + lane]));
        add4(a5, __ldg(&h4[s5 * 32 + lane]));
        add4(a6, __ldg(&h4[s6 * 32 + lane]));
        add4(a7, __ldg(&h4[s7 * 32 + lane]));
    }
    for (; e + 2 <= end; e += 2) {
        int s0 = __ldg(&g_csr_src[e + 0]);
        int s1 = __ldg(&g_csr_src[e + 1]);
        add4(a2, __ldg(&h4[s0 * 32 + lane]));
        add4(a3, __ldg(&h4[s1 * 32 + lane]));
    }
    if (e < end) {
        int s0 = __ldg(&g_csr_src[e]);
        add4(a4, __ldg(&h4[s0 * 32 + lane]));
    }
    add4(a0, a1); add4(a2, a3); add4(a4, a5); add4(a6, a7);
    add4(a0, a2); add4(a4, a6); add4(a0, a4);
    ((float4*)g_agg)[gw * 32 + lane] = a0;
}

// ---------------- persistent GEMM + bias + residual + ReLU + LayerNorm ----------------
// out[M,128] = agg @ W_rel + bias + Hin @ W_root  (K=256 stacked, tf32 mma)
struct GSmem {
    float w[32][32][36];   // [kk][lane][j] padded 32->36 for conflict-free LDS.128
    float a[128][132];     // A tile, padded stride
    float bias[128];
    float gamma[128];
    float beta[128];
};

__global__ void __launch_bounds__(256, 1)
gemm_kernel(const float* __restrict__ Hin,
            const float* __restrict__ bias,
            const float* __restrict__ gamma,
            const float* __restrict__ beta,
            float* __restrict__ out,
            int layer, int do_ln, int do_resid) {
    extern __shared__ char smem_raw[];
    GSmem& s = *(GSmem*)smem_raw;
    __shared__ int sh_tile;
    int tid = threadIdx.x, warp = tid >> 5, lane = tid & 31;
    int g = lane >> 2, tig = lane & 3;

    // load fragment-ordered weights once per CTA (persistent: once per SM per layer)
    const float* wsrc = g_wperm + layer * 32768;
    for (int i = tid; i < 32768; i += 256) {
        int kk = i >> 10, ln = (i >> 5) & 31, j = i & 31;
        s.w[kk][ln][j] = wsrc[i];
    }
    if (tid < 128) {
        s.bias[tid]  = bias[tid];
        s.gamma[tid] = gamma[tid];
        s.beta[tid]  = beta[tid];
    }
    const float4* __restrict__ H4 = (const float4*)Hin;
    const float4* __restrict__ G4 = (const float4*)g_agg;
    uint32_t a_smem_base;
    {
        void* p = &s.a[0][0];
        asm("{ .reg .u64 t; cvta.to.shared.u64 t, %1; cvt.u32.u64 %0, t; }"
            : "=r"(a_smem_base) : "l"(p));
    }

    int r0 = warp * 16 + g;

    while (true) {
        __syncthreads();                       // s.a free, sh_tile consumed
        if (tid == 0) sh_tile = atomicAdd(&g_tile_ctr[layer], 1);
        __syncthreads();
        int tile = sh_tile;
        if (tile >= NTILES) break;
        int rowBase = tile * 128;

        // ---- async load agg tile ----
        #pragma unroll
        for (int i = 0; i < 16; i++) {
            int f = tid + i * 256;
            int row = f >> 5, c4 = f & 31;
            int grow = rowBase + row;
            uint32_t daddr = a_smem_base + (row * 132 + c4 * 4) * 4;
            cp_async16(daddr, &G4[grow * 32 + c4], (grow < NN) ? 16 : 0);
        }
        cp_async_commit_wait0();
        __syncthreads();

        float c[16][4];
        #pragma unroll
        for (int nt = 0; nt < 16; nt++)
            #pragma unroll
            for (int j = 0; j < 4; j++) c[nt][j] = 0.f;

        // ---- phase 0: agg @ W_rel (kk 0..15) ----
        #pragma unroll 4
        for (int kks = 0; kks < 16; kks++) {
            uint32_t A0 = f2tf32(s.a[r0][kks * 8 + tig]);
            uint32_t A1 = f2tf32(s.a[r0 + 8][kks * 8 + tig]);
            uint32_t A2 = f2tf32(s.a[r0][kks * 8 + tig + 4]);
            uint32_t A3 = f2tf32(s.a[r0 + 8][kks * 8 + tig + 4]);
            const float4* wp = (const float4*)&s.w[kks][lane][0];
            #pragma unroll
            for (int q = 0; q < 8; q++) {
                float4 b = wp[q];
                mma_tf32(c[2 * q],     A0, A1, A2, A3, __float_as_uint(b.x), __float_as_uint(b.y));
                mma_tf32(c[2 * q + 1], A0, A1, A2, A3, __float_as_uint(b.z), __float_as_uint(b.w));
            }
        }
        __syncthreads();

        // ---- async load Hin tile ----
        #pragma unroll
        for (int i = 0; i < 16; i++) {
            int f = tid + i * 256;
            int row = f >> 5, c4 = f & 31;
            int grow = rowBase + row;
            uint32_t daddr = a_smem_base + (row * 132 + c4 * 4) * 4;
            cp_async16(daddr, &H4[grow * 32 + c4], (grow < NN) ? 16 : 0);
        }
        cp_async_commit_wait0();
        __syncthreads();

        // ---- phase 1: Hin @ W_root (kk 16..31) ----
        #pragma unroll 4
        for (int kks = 0; kks < 16; kks++) {
            uint32_t A0 = f2tf32(s.a[r0][kks * 8 + tig]);
            uint32_t A1 = f2tf32(s.a[r0 + 8][kks * 8 + tig]);
            uint32_t A2 = f2tf32(s.a[r0][kks * 8 + tig + 4]);
            uint32_t A3 = f2tf32(s.a[r0 + 8][kks * 8 + tig + 4]);
            const float4* wp = (const float4*)&s.w[16 + kks][lane][0];
            #pragma unroll
            for (int q = 0; q < 8; q++) {
                float4 b = wp[q];
                mma_tf32(c[2 * q],     A0, A1, A2, A3, __float_as_uint(b.x), __float_as_uint(b.y));
                mma_tf32(c[2 * q + 1], A0, A1, A2, A3, __float_as_uint(b.z), __float_as_uint(b.w));
            }
        }

        // ------------- epilogue -------------
        int rA = rowBase + warp * 16 + g;
        int rB = rA + 8;
        int lrA = warp * 16 + g;
        int lrB = lrA + 8;

        #pragma unroll
        for (int nt = 0; nt < 16; nt++) {
            int col = nt * 8 + 2 * tig;
            float b0 = s.bias[col], b1 = s.bias[col + 1];
            c[nt][0] += b0; c[nt][1] += b1;
            c[nt][2] += b0; c[nt][3] += b1;
        }
        if (do_resid) {
            // residual from SMEM copy of Hin tile (still resident in s.a)
            #pragma unroll
            for (int nt = 0; nt < 16; nt++) {
                int col = nt * 8 + 2 * tig;
                c[nt][0] += s.a[lrA][col];
                c[nt][1] += s.a[lrA][col + 1];
                c[nt][2] += s.a[lrB][col];
                c[nt][3] += s.a[lrB][col + 1];
            }
        }
        if (do_ln) {
            float sA = 0.f, qA = 0.f, sB = 0.f, qB = 0.f;
            #pragma unroll
            for (int nt = 0; nt < 16; nt++) {
                #pragma unroll
                for (int j = 0; j < 4; j++) c[nt][j] = fmaxf(c[nt][j], 0.f);
                sA += c[nt][0] + c[nt][1];
                qA += c[nt][0] * c[nt][0] + c[nt][1] * c[nt][1];
                sB += c[nt][2] + c[nt][3];
                qB += c[nt][2] * c[nt][2] + c[nt][3] * c[nt][3];
            }
            #pragma unroll
            for (int m = 1; m < 4; m <<= 1) {
                sA += __shfl_xor_sync(0xffffffffu, sA, m);
                qA += __shfl_xor_sync(0xffffffffu, qA, m);
                sB += __shfl_xor_sync(0xffffffffu, sB, m);
                qB += __shfl_xor_sync(0xffffffffu, qB, m);
            }
            float muA = sA * (1.f / 128.f);
            float vA = qA * (1.f / 128.f) - muA * muA;
            float rsA = rsqrtf(vA + LN_EPS);
            float muB = sB * (1.f / 128.f);
            float vB = qB * (1.f / 128.f) - muB * muB;
            float rsB = rsqrtf(vB + LN_EPS);
            #pragma unroll
            for (int nt = 0; nt < 16; nt++) {
                int col = nt * 8 + 2 * tig;
                float g0 = s.gamma[col], g1 = s.gamma[col + 1];
                float e0 = s.beta[col],  e1 = s.beta[col + 1];
                c[nt][0] = (c[nt][0] - muA) * rsA * g0 + e0;
                c[nt][1] = (c[nt][1] - muA) * rsA * g1 + e1;
                c[nt][2] = (c[nt][2] - muB) * rsB * g0 + e0;
                c[nt][3] = (c[nt][3] - muB) * rsB * g1 + e1;
            }
        }
        if (rA < NN) {
            #pragma unroll
            for (int nt = 0; nt < 16; nt++) {
                int col = nt * 8 + 2 * tig;
                *(float2*)(out + rA * 128 + col) = make_float2(c[nt][0], c[nt][1]);
            }
        }
        if (rB < NN) {
            #pragma unroll
            for (int nt = 0; nt < 16; nt++) {
                int col = nt * 8 + 2 * tig;
                *(float2*)(out + rB * 128 + col) = make_float2(c[nt][2], c[nt][3]);
            }
        }
    }
}

// ---------------- host driver ----------------
extern "C" void kernel_launch(void* const* d_in, const int* in_sizes, int n_in,
                              void* d_out, int out_size) {
    const float* in_feat = (const float*)d_in[0];
    const int*   ei      = (const int*)d_in[1];
    const float* W_rel   = (const float*)d_in[2];
    const float* b_rel   = (const float*)d_in[3];
    const float* W_root  = (const float*)d_in[4];
    const float* gamma   = (const float*)d_in[5];
    const float* beta    = (const float*)d_in[6];
    float* out = (float*)d_out;

    const int* src = ei;
    const int* dst = ei + EE;

    cudaFuncSetAttribute(gemm_kernel, cudaFuncAttributeMaxDynamicSharedMemorySize,
                         (int)sizeof(GSmem));

    float* bufA = nullptr;
    float* bufB = nullptr;
    cudaGetSymbolAddress((void**)&bufA, g_bufA);
    cudaGetSymbolAddress((void**)&bufB, g_bufB);

    // CSR build + weight prep (once per launch; reused by all 4 layers)
    zero_kernel<<<(NN + 255) / 256, 256>>>();
    hist_kernel<<<(EE + 255) / 256, 256>>>(dst);
    scan_kernel<<<1, 1024>>>();
    scatter_kernel<<<(EE + 255) / 256, 256>>>(src, dst);
    wprep_kernel<<<(LL * 32768) / 256, 256>>>(W_rel, W_root);

    const float* hin = in_feat;
    for (int l = 0; l < LL; l++) {
        agg_kernel<<<(NN * 32 + 255) / 256, 256>>>(hin);
        float* hout = (l == LL - 1) ? out : ((l & 1) ? bufB : bufA);
        int do_ln = (l < LL - 1) ? 1 : 0;
        int do_resid = (l >= 1 && l <= LL - 2) ? 1 : 0;
        gemm_kernel<<<GRID_PERSIST, 256, sizeof(GSmem)>>>(
            hin, b_rel + l * DD, gamma, beta, hout, l, do_ln, do_resid);
        hin = hout;
    }
}